// round 13
// baseline (speedup 1.0000x reference)
#include <cuda_runtime.h>
#include <cuda_bf16.h>
#include <mma.h>
#include <math.h>

using namespace nvcuda;

// Problem constants (fixed by setup_inputs)
#define NMAX 50000
#define NPAD 50048
#define EMAX 600000
#define D 128
#define NUM_INNER 2   // number_of_layers = 4 -> 2 inner LEConv layers
#define CS_BLOCKS 128 // colstats partial blocks

// ---------------- scratch (device globals; no allocation allowed) -------------
__device__ __nv_bfloat16 g_Hhi[NPAD * D];  // activations, bf16 high part
__device__ __nv_bfloat16 g_Hlo[NPAD * D];  // activations, bf16 low part
__device__ float g_R1[NPAD * D];           // raw lin1(x)
__device__ float g_R23[NPAD * D];          // lin3 + b3 - ws*lin2 (pre-combined)
__device__ float g_wsum[NMAX];
__device__ float g_aO[NMAX];
__device__ float g_psum[CS_BLOCKS * D];
__device__ float g_psq[CS_BLOCKS * D];
__device__ float g_colmean[D];
__device__ float g_colinv[D];
// pre-converted weights: 6 slots (in:W1,W2,W3 ; h:W1,W2,W3), each 128x128 bf16
__device__ __nv_bfloat16 g_Whi[6 * D * D];
__device__ __nv_bfloat16 g_Wlo[6 * D * D];
// CSR
__device__ int   g_deg[NMAX];
__device__ int   g_rowptr[NMAX + 1];
__device__ int   g_cursor[NMAX];
__device__ int   g_bsum[256];
__device__ int   g_csrc[EMAX];
__device__ float g_cw[EMAX];

// ---------------- utility kernels -------------------------------------------
__global__ void zero_i(int* p, int n) {
    int i = blockIdx.x * blockDim.x + threadIdx.x;
    if (i < n) p[i] = 0;
}

// per-column partial sums (no atomics, no pre-zero)
__global__ void colstats_kernel(const float* __restrict__ x, int N) {
    int c = threadIdx.x;
    float s = 0.f, ss = 0.f;
    for (int r = blockIdx.x; r < N; r += gridDim.x) {
        float v = x[(size_t)r * D + c];
        s += v;
        ss += v * v;
    }
    g_psum[blockIdx.x * D + c] = s;
    g_psq[blockIdx.x * D + c] = ss;
}

__global__ void colfinal_kernel(int N) {
    int c = threadIdx.x;
    float s = 0.f, ss = 0.f;
    for (int b = 0; b < CS_BLOCKS; b++) {
        s += g_psum[b * D + c];
        ss += g_psq[b * D + c];
    }
    float mean = s / (float)N;
    float var = (ss - (float)N * mean * mean) / (float)(N - 1);
    var = fmaxf(var, 0.f);
    g_colmean[c] = mean;
    g_colinv[c] = 1.f / (sqrtf(var) + 1e-6f);
}

__device__ __forceinline__ void write_hilo(size_t base, float y0, float y1, float y2, float y3) {
    __nv_bfloat16 h0 = __float2bfloat16(y0), h1 = __float2bfloat16(y1);
    __nv_bfloat16 h2 = __float2bfloat16(y2), h3 = __float2bfloat16(y3);
    *reinterpret_cast<__nv_bfloat162*>(&g_Hhi[base]) = __nv_bfloat162(h0, h1);
    *reinterpret_cast<__nv_bfloat162*>(&g_Hhi[base + 2]) = __nv_bfloat162(h2, h3);
    __nv_bfloat16 l0 = __float2bfloat16(y0 - __bfloat162float(h0));
    __nv_bfloat16 l1 = __float2bfloat16(y1 - __bfloat162float(h1));
    __nv_bfloat16 l2 = __float2bfloat16(y2 - __bfloat162float(h2));
    __nv_bfloat16 l3 = __float2bfloat16(y3 - __bfloat162float(h3));
    *reinterpret_cast<__nv_bfloat162*>(&g_Hlo[base]) = __nv_bfloat162(l0, l1);
    *reinterpret_cast<__nv_bfloat162*>(&g_Hlo[base + 2]) = __nv_bfloat162(l2, l3);
}

__global__ void normalize_kernel(const float4* __restrict__ x4, int n4) {
    int i = blockIdx.x * blockDim.x + threadIdx.x;
    if (i >= n4) return;
    int c = (i & 31) * 4;
    float4 v = x4[i];
    float y0 = (v.x - g_colmean[c + 0]) * g_colinv[c + 0];
    float y1 = (v.y - g_colmean[c + 1]) * g_colinv[c + 1];
    float y2 = (v.z - g_colmean[c + 2]) * g_colinv[c + 2];
    float y3 = (v.w - g_colmean[c + 3]) * g_colinv[c + 3];
    write_hilo((size_t)i * 4, y0, y1, y2, y3);
}

// ---------------- weight pre-conversion (6 matrices, once per call) ----------
struct WPtrs { const float* w[6]; };

__global__ void convert_w_kernel(WPtrs wp) {
    int slot = blockIdx.y;
    const float* W = wp.w[slot];
    int i = blockIdx.x * blockDim.x + threadIdx.x;
    float4 v = *reinterpret_cast<const float4*>(W + i * 4);
    size_t o = (size_t)slot * D * D + i * 4;
    __nv_bfloat16 h0 = __float2bfloat16(v.x), h1 = __float2bfloat16(v.y);
    __nv_bfloat16 h2 = __float2bfloat16(v.z), h3 = __float2bfloat16(v.w);
    g_Whi[o + 0] = h0; g_Whi[o + 1] = h1; g_Whi[o + 2] = h2; g_Whi[o + 3] = h3;
    g_Wlo[o + 0] = __float2bfloat16(v.x - __bfloat162float(h0));
    g_Wlo[o + 1] = __float2bfloat16(v.y - __bfloat162float(h1));
    g_Wlo[o + 2] = __float2bfloat16(v.z - __bfloat162float(h2));
    g_Wlo[o + 3] = __float2bfloat16(v.w - __bfloat162float(h3));
}

// ---------------- CSR build --------------------------------------------------
__global__ void deg_hist_kernel(const int* __restrict__ dst, int E) {
    int e = blockIdx.x * blockDim.x + threadIdx.x;
    if (e < E) atomicAdd(&g_deg[dst[e]], 1);
}

__global__ void scan1_kernel(int N) {
    __shared__ int sh[256];
    int i = blockIdx.x * 256 + threadIdx.x;
    int v = (i < N) ? g_deg[i] : 0;
    sh[threadIdx.x] = v;
    __syncthreads();
#pragma unroll
    for (int o = 1; o < 256; o <<= 1) {
        int t = (threadIdx.x >= o) ? sh[threadIdx.x - o] : 0;
        __syncthreads();
        sh[threadIdx.x] += t;
        __syncthreads();
    }
    if (threadIdx.x == 255) g_bsum[blockIdx.x] = sh[255];
}

__global__ void scan2_kernel(int nb) {
    __shared__ int sh[256];
    int v = (threadIdx.x < nb) ? g_bsum[threadIdx.x] : 0;
    sh[threadIdx.x] = v;
    __syncthreads();
#pragma unroll
    for (int o = 1; o < 256; o <<= 1) {
        int t = (threadIdx.x >= o) ? sh[threadIdx.x - o] : 0;
        __syncthreads();
        sh[threadIdx.x] += t;
        __syncthreads();
    }
    if (threadIdx.x < nb) g_bsum[threadIdx.x] = sh[threadIdx.x] - v;  // exclusive
}

__global__ void scan3_kernel(int N) {
    __shared__ int sh[256];
    int i = blockIdx.x * 256 + threadIdx.x;
    int v = (i < N) ? g_deg[i] : 0;
    sh[threadIdx.x] = v;
    __syncthreads();
#pragma unroll
    for (int o = 1; o < 256; o <<= 1) {
        int t = (threadIdx.x >= o) ? sh[threadIdx.x - o] : 0;
        __syncthreads();
        sh[threadIdx.x] += t;
        __syncthreads();
    }
    int excl = sh[threadIdx.x] - v + g_bsum[blockIdx.x];
    if (i < N) {
        g_rowptr[i] = excl;
        g_cursor[i] = excl;
        if (i == N - 1) g_rowptr[N] = excl + v;
    }
}

__global__ void csr_fill_kernel(const int* __restrict__ src, const int* __restrict__ dst,
                                const float* __restrict__ w, int E) {
    int e = blockIdx.x * blockDim.x + threadIdx.x;
    if (e >= E) return;
    int pos = atomicAdd(&g_cursor[dst[e]], 1);
    g_csrc[pos] = src[e];
    g_cw[pos] = w[e];
}

__global__ void wsum_csr_kernel(int N) {
    int r = blockIdx.x * blockDim.x + threadIdx.x;
    if (r >= N) return;
    int beg = g_rowptr[r], end = g_rowptr[r + 1];
    float s = 0.f;
    for (int i = beg; i < end; i++) s += g_cw[i];
    g_wsum[r] = s;
}

// ---------------- 3-GEMM layer kernel with fused R23 combine -----------------
// Phase 0: W1 -> store R1 raw immediately (acc1 dead after).
// Phases 1/2: acc2, acc3 stay in registers (64 regs; NO min-blocks cap ->
// no spill; smem alone limits to 2 CTA/SM). After last MMA all smem is dead:
// dump acc2/acc3 there, combine R23 = acc3 + b3 - ws*acc2, single store.
#define XLD 136
#define FLD 132   // float staging row stride
#define SM_XHI 0
#define SM_XLO 17408
#define SM_WHI 34816
#define SM_WLO 69632
#define SM_TOTAL 104448

__global__ __launch_bounds__(256) void gemm3_raw(
    const __nv_bfloat16* __restrict__ Hhi, const __nv_bfloat16* __restrict__ Hlo,
    int wslot, const float* __restrict__ b3,
    float* __restrict__ R1, float* __restrict__ R23, int M)
{
    extern __shared__ char smem[];
    __nv_bfloat16* Xhi = (__nv_bfloat16*)(smem + SM_XHI);
    __nv_bfloat16* Xlo = (__nv_bfloat16*)(smem + SM_XLO);
    __nv_bfloat16* Whi = (__nv_bfloat16*)(smem + SM_WHI);
    __nv_bfloat16* Wlo = (__nv_bfloat16*)(smem + SM_WLO);
    float* F2 = (float*)(smem + SM_XHI);   // reuse X region after MMAs
    float* F3 = (float*)(smem + SM_WHI);   // reuse W region after MMAs

    int tid = threadIdx.x;
    int wid = tid >> 5;
    int warpM = wid & 1;      // 2 x 32-row slices
    int warpN = wid >> 1;     // 4 x 32-col slices
    int m0 = blockIdx.x * 64;

    // stage X tile (64 x 128, hi/lo), zero-fill OOB rows
    for (int idx = tid; idx < 64 * 16; idx += 256) {
        int row = idx >> 4, c8 = (idx & 15) * 8;
        float4 zero = make_float4(0.f, 0.f, 0.f, 0.f);
        float4 vh = zero, vl = zero;
        if (m0 + row < M) {
            vh = *reinterpret_cast<const float4*>(Hhi + (size_t)(m0 + row) * D + c8);
            vl = *reinterpret_cast<const float4*>(Hlo + (size_t)(m0 + row) * D + c8);
        }
        *reinterpret_cast<float4*>(Xhi + row * XLD + c8) = vh;
        *reinterpret_cast<float4*>(Xlo + row * XLD + c8) = vl;
    }

    wmma::fragment<wmma::accumulator, 16, 16, 16, float> acc2[2][2], acc3[2][2];

    for (int widx = 0; widx < 3; widx++) {
        __syncthreads();   // X staged (first) / prior-phase MMAs done reading W
        const __nv_bfloat16* Gh = g_Whi + (size_t)(wslot + widx) * D * D;
        const __nv_bfloat16* Gl = g_Wlo + (size_t)(wslot + widx) * D * D;
        for (int idx = tid; idx < 128 * 16; idx += 256) {
            int row = idx >> 4, c8 = (idx & 15) * 8;
            *reinterpret_cast<float4*>(Whi + row * XLD + c8) =
                *reinterpret_cast<const float4*>(Gh + row * D + c8);
            *reinterpret_cast<float4*>(Wlo + row * XLD + c8) =
                *reinterpret_cast<const float4*>(Gl + row * D + c8);
        }
        __syncthreads();

        // phase-local accumulator for widx==0; persistent for 1/2
        wmma::fragment<wmma::accumulator, 16, 16, 16, float> acc0[2][2];
        wmma::fragment<wmma::accumulator, 16, 16, 16, float> (*acc)[2] =
            (widx == 0) ? acc0 : (widx == 1) ? acc2 : acc3;
#pragma unroll
        for (int i = 0; i < 2; i++)
#pragma unroll
            for (int j = 0; j < 2; j++) wmma::fill_fragment(acc[i][j], 0.f);

#pragma unroll
        for (int kk = 0; kk < 8; kk++) {
            wmma::fragment<wmma::matrix_a, 16, 16, 16, __nv_bfloat16, wmma::row_major> ah[2], al[2];
#pragma unroll
            for (int i = 0; i < 2; i++) {
                int off = (warpM * 32 + i * 16) * XLD + kk * 16;
                wmma::load_matrix_sync(ah[i], Xhi + off, XLD);
                wmma::load_matrix_sync(al[i], Xlo + off, XLD);
            }
#pragma unroll
            for (int j = 0; j < 2; j++) {
                wmma::fragment<wmma::matrix_b, 16, 16, 16, __nv_bfloat16, wmma::row_major> bh, bl;
                int off = (kk * 16) * XLD + warpN * 32 + j * 16;
                wmma::load_matrix_sync(bh, Whi + off, XLD);
                wmma::load_matrix_sync(bl, Wlo + off, XLD);
#pragma unroll
                for (int i = 0; i < 2; i++) {
                    wmma::mma_sync(acc[i][j], ah[i], bh, acc[i][j]);
                    wmma::mma_sync(acc[i][j], ah[i], bl, acc[i][j]);
                    wmma::mma_sync(acc[i][j], al[i], bh, acc[i][j]);
                }
            }
        }

        if (widx == 0) {
            // store raw lin1 directly (buffers NPAD-sized -> no guard needed)
#pragma unroll
            for (int i = 0; i < 2; i++)
#pragma unroll
                for (int j = 0; j < 2; j++)
                    wmma::store_matrix_sync(
                        R1 + (size_t)(m0 + warpM * 32 + i * 16) * D + warpN * 32 + j * 16,
                        acc0[i][j], D, wmma::mem_row_major);
        }
    }

    // all MMAs done; X and W smem regions dead. Dump acc2/acc3 and combine.
    __syncthreads();
#pragma unroll
    for (int i = 0; i < 2; i++)
#pragma unroll
        for (int j = 0; j < 2; j++) {
            int off = (warpM * 32 + i * 16) * FLD + warpN * 32 + j * 16;
            wmma::store_matrix_sync(F2 + off, acc2[i][j], FLD, wmma::mem_row_major);
            wmma::store_matrix_sync(F3 + off, acc3[i][j], FLD, wmma::mem_row_major);
        }
    __syncthreads();

    for (int idx = tid; idx < 64 * 32; idx += 256) {
        int row = idx >> 5, c4 = (idx & 31) * 4;
        int gm = m0 + row;
        if (gm >= M) continue;
        float ws = g_wsum[gm];
        float4 v2 = *reinterpret_cast<const float4*>(F2 + row * FLD + c4);
        float4 v3 = *reinterpret_cast<const float4*>(F3 + row * FLD + c4);
        float4 o;
        o.x = v3.x + b3[c4 + 0] - ws * v2.x;
        o.y = v3.y + b3[c4 + 1] - ws * v2.y;
        o.z = v3.z + b3[c4 + 2] - ws * v2.z;
        o.w = v3.w + b3[c4 + 3] - ws * v2.w;
        *reinterpret_cast<float4*>(R23 + (size_t)gm * D + c4) = o;
    }
}

// ---------- gather + LayerNorm + LeakyReLU fused (warp per dst row) ----------
// acc = R23[row] + ws*b1 + sum_e w_e * R1[src_e]; LN+leaky -> Hhi/Hlo
__global__ __launch_bounds__(256) void gather_ln_kernel(
    const float* __restrict__ R1, const float* __restrict__ R23,
    const float* __restrict__ b1,
    const float* __restrict__ g, const float* __restrict__ beta, int N)
{
    int row = (blockIdx.x * blockDim.x + threadIdx.x) >> 5;
    int lane = threadIdx.x & 31;
    if (row >= N) return;

    int c = lane * 4;
    size_t base = (size_t)row * D + c;
    float ws = g_wsum[row];
    float4 r23 = *reinterpret_cast<const float4*>(R23 + base);
    float4 b1v = *reinterpret_cast<const float4*>(b1 + c);
    float4 acc;
    acc.x = r23.x + ws * b1v.x;
    acc.y = r23.y + ws * b1v.y;
    acc.z = r23.z + ws * b1v.z;
    acc.w = r23.w + ws * b1v.w;

    int beg = g_rowptr[row], end = g_rowptr[row + 1];
    for (int chunk = beg; chunk < end; chunk += 32) {
        int idx = chunk + lane;
        int s = 0; float wv = 0.f;
        if (idx < end) { s = g_csrc[idx]; wv = g_cw[idx]; }
        int cnt = min(32, end - chunk);
#pragma unroll 4
        for (int j = 0; j < cnt; j++) {
            int ss = __shfl_sync(0xFFFFFFFFu, s, j);
            float ww = __shfl_sync(0xFFFFFFFFu, wv, j);
            float4 v = *reinterpret_cast<const float4*>(R1 + (size_t)ss * D + c);
            acc.x += ww * v.x;
            acc.y += ww * v.y;
            acc.z += ww * v.z;
            acc.w += ww * v.w;
        }
    }

    float v0 = acc.x, v1 = acc.y, v2 = acc.z, v3 = acc.w;
    float s = v0 + v1 + v2 + v3;
    float ss = v0 * v0 + v1 * v1 + v2 * v2 + v3 * v3;
#pragma unroll
    for (int o = 16; o; o >>= 1) {
        s += __shfl_xor_sync(0xFFFFFFFFu, s, o);
        ss += __shfl_xor_sync(0xFFFFFFFFu, ss, o);
    }
    float mean = s * (1.f / (float)D);
    float var = ss * (1.f / (float)D) - mean * mean;
    float inv = rsqrtf(var + 1e-5f);
    float4 gg = *reinterpret_cast<const float4*>(g + c);
    float4 bb = *reinterpret_cast<const float4*>(beta + c);
    float y0 = (v0 - mean) * inv * gg.x + bb.x;
    float y1 = (v1 - mean) * inv * gg.y + bb.y;
    float y2 = (v2 - mean) * inv * gg.z + bb.z;
    float y3 = (v3 - mean) * inv * gg.w + bb.w;
    y0 = y0 > 0.f ? y0 : 0.1f * y0;
    y1 = y1 > 0.f ? y1 : 0.1f * y1;
    y2 = y2 > 0.f ? y2 : 0.1f * y2;
    y3 = y3 > 0.f ? y3 : 0.1f * y3;
    write_hilo(base, y0, y1, y2, y3);
}

// ---------------- final layer (D -> 1): warp-per-row GEMV --------------------
__global__ void final_gemv_kernel(
    const float* __restrict__ W1, const float* __restrict__ b1,
    const float* __restrict__ W2,
    const float* __restrict__ W3, const float* __restrict__ b3,
    float* __restrict__ out, int N)
{
    int row = (blockIdx.x * blockDim.x + threadIdx.x) >> 5;
    int lane = threadIdx.x & 31;
    if (row >= N) return;
    size_t base = (size_t)row * D + lane * 4;
    float h[4];
#pragma unroll
    for (int k = 0; k < 4; k++)
        h[k] = __bfloat162float(g_Hhi[base + k]) + __bfloat162float(g_Hlo[base + k]);
    float4 w1 = *reinterpret_cast<const float4*>(W1 + lane * 4);
    float4 w2 = *reinterpret_cast<const float4*>(W2 + lane * 4);
    float4 w3 = *reinterpret_cast<const float4*>(W3 + lane * 4);
    float s1 = h[0] * w1.x + h[1] * w1.y + h[2] * w1.z + h[3] * w1.w;
    float s2 = h[0] * w2.x + h[1] * w2.y + h[2] * w2.z + h[3] * w2.w;
    float s3 = h[0] * w3.x + h[1] * w3.y + h[2] * w3.z + h[3] * w3.w;
#pragma unroll
    for (int o = 16; o; o >>= 1) {
        s1 += __shfl_xor_sync(0xFFFFFFFFu, s1, o);
        s2 += __shfl_xor_sync(0xFFFFFFFFu, s2, o);
        s3 += __shfl_xor_sync(0xFFFFFFFFu, s3, o);
    }
    if (lane == 0) {
        g_aO[row] = s1 + b1[0];
        out[row] = (s3 + b3[0]) - g_wsum[row] * s2;
    }
}

__global__ void final_gather_sigmoid_kernel(float* __restrict__ out, int N) {
    int r = blockIdx.x * blockDim.x + threadIdx.x;
    if (r >= N) return;
    float v = out[r];
    int beg = g_rowptr[r], end = g_rowptr[r + 1];
    for (int i = beg; i < end; i++) v += g_cw[i] * g_aO[g_csrc[i]];
    out[r] = 1.f / (1.f + expf(-v));
}

// ---------------- driver -----------------------------------------------------
extern "C" void kernel_launch(void* const* d_in, const int* in_sizes, int n_in,
                              void* d_out, int out_size)
{
    const float* x     = (const float*)d_in[0];
    const float* ew    = (const float*)d_in[1];
    const float* W1_in = (const float*)d_in[2];
    const float* b1_in = (const float*)d_in[3];
    const float* W2_in = (const float*)d_in[4];
    const float* W3_in = (const float*)d_in[5];
    const float* b3_in = (const float*)d_in[6];
    const float* W1_h  = (const float*)d_in[7];
    const float* b1_h  = (const float*)d_in[8];
    const float* W2_h  = (const float*)d_in[9];
    const float* W3_h  = (const float*)d_in[10];
    const float* b3_h  = (const float*)d_in[11];
    const float* W1_o  = (const float*)d_in[12];
    const float* b1_o  = (const float*)d_in[13];
    const float* W2_o  = (const float*)d_in[14];
    const float* W3_o  = (const float*)d_in[15];
    const float* b3_o  = (const float*)d_in[16];
    const float* g1    = (const float*)d_in[17];
    const float* be1   = (const float*)d_in[18];
    const float* g2    = (const float*)d_in[19];
    const float* be2   = (const float*)d_in[20];
    const int*   ei    = (const int*)d_in[21];

    int N = in_sizes[0] / D;
    int E = in_sizes[1];
    const int* src = ei;
    const int* dst = ei + E;
    float* out = (float*)d_out;

    float *R1, *R23;
    int *deg;
    __nv_bfloat16 *Hhi, *Hlo;
    cudaGetSymbolAddress((void**)&Hhi, g_Hhi);
    cudaGetSymbolAddress((void**)&Hlo, g_Hlo);
    cudaGetSymbolAddress((void**)&R1, g_R1);
    cudaGetSymbolAddress((void**)&R23, g_R23);
    cudaGetSymbolAddress((void**)&deg, g_deg);

    static int smemSet = 0;
    if (!smemSet) {
        cudaFuncSetAttribute(gemm3_raw, cudaFuncAttributeMaxDynamicSharedMemorySize, SM_TOTAL);
        smemSet = 1;
    }

    int n4 = N * (D / 4);
    int nb = (N + 255) / 256;

    // ---- input standardization -> Hhi/Hlo (atomic-free) ----
    colstats_kernel<<<CS_BLOCKS, 128>>>(x, N);
    colfinal_kernel<<<1, 128>>>(N);
    normalize_kernel<<<(n4 + 255) / 256, 256>>>((const float4*)x, n4);

    // ---- weight pre-conversion ----
    WPtrs wp;
    wp.w[0] = W1_in; wp.w[1] = W2_in; wp.w[2] = W3_in;
    wp.w[3] = W1_h;  wp.w[4] = W2_h;  wp.w[5] = W3_h;
    convert_w_kernel<<<dim3(D * D / 4 / 256, 6), 256>>>(wp);

    // ---- CSR build ----
    zero_i<<<nb, 256>>>(deg, N);
    deg_hist_kernel<<<(E + 255) / 256, 256>>>(dst, E);
    scan1_kernel<<<nb, 256>>>(N);
    scan2_kernel<<<1, 256>>>(nb);
    scan3_kernel<<<nb, 256>>>(N);
    csr_fill_kernel<<<(E + 255) / 256, 256>>>(src, dst, ew, E);
    wsum_csr_kernel<<<nb, 256>>>(N);

    // ---- 3 full LEConv layers ----
    struct LW { int slot; const float *b1, *b3, *g, *be; };
    LW layers[1 + NUM_INNER];
    layers[0] = {0, b1_in, b3_in, g1, be1};
    for (int l = 1; l <= NUM_INNER; l++)
        layers[l] = {3, b1_h, b3_h, g2, be2};

    int gemmGrid = (N + 63) / 64;
    for (int l = 0; l < 1 + NUM_INNER; l++) {
        gemm3_raw<<<gemmGrid, 256, SM_TOTAL>>>(Hhi, Hlo, layers[l].slot, layers[l].b3,
                                               R1, R23, N);
        gather_ln_kernel<<<(N + 7) / 8, 256>>>(R1, R23, layers[l].b1,
                                               layers[l].g, layers[l].be, N);
    }

    // ---- output layer (D -> 1) + sigmoid ----
    final_gemv_kernel<<<(N + 7) / 8, 256>>>(W1_o, b1_o, W2_o, W3_o, b3_o, out, N);
    final_gather_sigmoid_kernel<<<nb, 256>>>(out, N);
}

// round 14
// speedup vs baseline: 1.4990x; 1.4990x over previous
#include <cuda_runtime.h>
#include <cuda_bf16.h>
#include <mma.h>
#include <math.h>

using namespace nvcuda;

// Problem constants (fixed by setup_inputs)
#define NMAX 50000
#define NPAD 50048
#define EMAX 600000
#define D 128
#define NUM_INNER 2   // number_of_layers = 4 -> 2 inner LEConv layers

// ---------------- scratch (device globals; no allocation allowed) -------------
__device__ __nv_bfloat16 g_Hhi[NPAD * D];  // activations, bf16 high part
__device__ __nv_bfloat16 g_Hlo[NPAD * D];  // activations, bf16 low part
__device__ float g_R1[NPAD * D];           // raw lin1(x)
__device__ float g_R2[NPAD * D];           // raw lin2(x)
__device__ float g_R3[NPAD * D];           // raw lin3(x)
__device__ float g_wsum[NMAX];
__device__ float g_aO[NMAX];
__device__ float g_colsum[D];
__device__ float g_colsumsq[D];
__device__ float g_colmean[D];
__device__ float g_colinv[D];
// pre-converted weights: 6 slots (in:W1,W2,W3 ; h:W1,W2,W3), each 128x128 bf16
__device__ __nv_bfloat16 g_Whi[6 * D * D];
__device__ __nv_bfloat16 g_Wlo[6 * D * D];
// CSR
__device__ int   g_deg[NMAX];
__device__ int   g_rowptr[NMAX + 1];
__device__ int   g_cursor[NMAX];
__device__ int   g_bsum[256];
__device__ int   g_csrc[EMAX];
__device__ float g_cw[EMAX];

// ---------------- utility kernels -------------------------------------------
__global__ void zero_f(float* p, int n) {
    int i = blockIdx.x * blockDim.x + threadIdx.x;
    if (i < n) p[i] = 0.f;
}
__global__ void zero_i(int* p, int n) {
    int i = blockIdx.x * blockDim.x + threadIdx.x;
    if (i < n) p[i] = 0;
}

__global__ void colstats_kernel(const float* __restrict__ x, int N) {
    int c = threadIdx.x;
    float s = 0.f, ss = 0.f;
    for (int r = blockIdx.x; r < N; r += gridDim.x) {
        float v = x[(size_t)r * D + c];
        s += v;
        ss += v * v;
    }
    atomicAdd(&g_colsum[c], s);
    atomicAdd(&g_colsumsq[c], ss);
}

__global__ void colfinal_kernel(int N) {
    int c = threadIdx.x;
    float mean = g_colsum[c] / (float)N;
    float var = (g_colsumsq[c] - (float)N * mean * mean) / (float)(N - 1);
    var = fmaxf(var, 0.f);
    g_colmean[c] = mean;
    g_colinv[c] = 1.f / (sqrtf(var) + 1e-6f);
}

__device__ __forceinline__ void write_hilo(size_t base, float y0, float y1, float y2, float y3) {
    __nv_bfloat16 h0 = __float2bfloat16(y0), h1 = __float2bfloat16(y1);
    __nv_bfloat16 h2 = __float2bfloat16(y2), h3 = __float2bfloat16(y3);
    *reinterpret_cast<__nv_bfloat162*>(&g_Hhi[base]) = __nv_bfloat162(h0, h1);
    *reinterpret_cast<__nv_bfloat162*>(&g_Hhi[base + 2]) = __nv_bfloat162(h2, h3);
    __nv_bfloat16 l0 = __float2bfloat16(y0 - __bfloat162float(h0));
    __nv_bfloat16 l1 = __float2bfloat16(y1 - __bfloat162float(h1));
    __nv_bfloat16 l2 = __float2bfloat16(y2 - __bfloat162float(h2));
    __nv_bfloat16 l3 = __float2bfloat16(y3 - __bfloat162float(h3));
    *reinterpret_cast<__nv_bfloat162*>(&g_Hlo[base]) = __nv_bfloat162(l0, l1);
    *reinterpret_cast<__nv_bfloat162*>(&g_Hlo[base + 2]) = __nv_bfloat162(l2, l3);
}

// x -> standardized, written as bf16 hi/lo
__global__ void normalize_kernel(const float4* __restrict__ x4, int n4) {
    int i = blockIdx.x * blockDim.x + threadIdx.x;
    if (i >= n4) return;
    int c = (i & 31) * 4;
    float4 v = x4[i];
    float y0 = (v.x - g_colmean[c + 0]) * g_colinv[c + 0];
    float y1 = (v.y - g_colmean[c + 1]) * g_colinv[c + 1];
    float y2 = (v.z - g_colmean[c + 2]) * g_colinv[c + 2];
    float y3 = (v.w - g_colmean[c + 3]) * g_colinv[c + 3];
    write_hilo((size_t)i * 4, y0, y1, y2, y3);
}

// ---------------- weight pre-conversion (6 matrices, once per call) ----------
struct WPtrs { const float* w[6]; };

__global__ void convert_w_kernel(WPtrs wp) {
    int slot = blockIdx.y;
    const float* W = wp.w[slot];
    int i = blockIdx.x * blockDim.x + threadIdx.x;   // 0 .. D*D/4-1 (float4 units)
    float4 v = *reinterpret_cast<const float4*>(W + i * 4);
    size_t o = (size_t)slot * D * D + i * 4;
    __nv_bfloat16 h0 = __float2bfloat16(v.x), h1 = __float2bfloat16(v.y);
    __nv_bfloat16 h2 = __float2bfloat16(v.z), h3 = __float2bfloat16(v.w);
    g_Whi[o + 0] = h0; g_Whi[o + 1] = h1; g_Whi[o + 2] = h2; g_Whi[o + 3] = h3;
    g_Wlo[o + 0] = __float2bfloat16(v.x - __bfloat162float(h0));
    g_Wlo[o + 1] = __float2bfloat16(v.y - __bfloat162float(h1));
    g_Wlo[o + 2] = __float2bfloat16(v.z - __bfloat162float(h2));
    g_Wlo[o + 3] = __float2bfloat16(v.w - __bfloat162float(h3));
}

// ---------------- CSR build --------------------------------------------------
__global__ void deg_hist_kernel(const int* __restrict__ dst, int E) {
    int e = blockIdx.x * blockDim.x + threadIdx.x;
    if (e < E) atomicAdd(&g_deg[dst[e]], 1);
}

__global__ void scan1_kernel(int N) {
    __shared__ int sh[256];
    int i = blockIdx.x * 256 + threadIdx.x;
    int v = (i < N) ? g_deg[i] : 0;
    sh[threadIdx.x] = v;
    __syncthreads();
#pragma unroll
    for (int o = 1; o < 256; o <<= 1) {
        int t = (threadIdx.x >= o) ? sh[threadIdx.x - o] : 0;
        __syncthreads();
        sh[threadIdx.x] += t;
        __syncthreads();
    }
    if (threadIdx.x == 255) g_bsum[blockIdx.x] = sh[255];
}

__global__ void scan2_kernel(int nb) {
    __shared__ int sh[256];
    int v = (threadIdx.x < nb) ? g_bsum[threadIdx.x] : 0;
    sh[threadIdx.x] = v;
    __syncthreads();
#pragma unroll
    for (int o = 1; o < 256; o <<= 1) {
        int t = (threadIdx.x >= o) ? sh[threadIdx.x - o] : 0;
        __syncthreads();
        sh[threadIdx.x] += t;
        __syncthreads();
    }
    if (threadIdx.x < nb) g_bsum[threadIdx.x] = sh[threadIdx.x] - v;  // exclusive
}

__global__ void scan3_kernel(int N) {
    __shared__ int sh[256];
    int i = blockIdx.x * 256 + threadIdx.x;
    int v = (i < N) ? g_deg[i] : 0;
    sh[threadIdx.x] = v;
    __syncthreads();
#pragma unroll
    for (int o = 1; o < 256; o <<= 1) {
        int t = (threadIdx.x >= o) ? sh[threadIdx.x - o] : 0;
        __syncthreads();
        sh[threadIdx.x] += t;
        __syncthreads();
    }
    int excl = sh[threadIdx.x] - v + g_bsum[blockIdx.x];
    if (i < N) {
        g_rowptr[i] = excl;
        g_cursor[i] = excl;
        if (i == N - 1) g_rowptr[N] = excl + v;
    }
}

__global__ void csr_fill_kernel(const int* __restrict__ src, const int* __restrict__ dst,
                                const float* __restrict__ w, int E) {
    int e = blockIdx.x * blockDim.x + threadIdx.x;
    if (e >= E) return;
    int pos = atomicAdd(&g_cursor[dst[e]], 1);
    g_csrc[pos] = src[e];
    g_cw[pos] = w[e];
}

__global__ void wsum_csr_kernel(int N) {
    int r = blockIdx.x * blockDim.x + threadIdx.x;
    if (r >= N) return;
    int beg = g_rowptr[r], end = g_rowptr[r + 1];
    float s = 0.f;
    for (int i = beg; i < end; i++) s += g_cw[i];
    g_wsum[r] = s;
}

// ---------------- lean 3-GEMM layer kernel (R7 structure, bf16 W staging) ----
// X + W in smem (104KB, 2 CTA/SM). W staged as pure bf16 copy from the
// pre-converted global arrays — no fp32 reads, no cvt chains.
#define XLD 136
#define SM_XHI 0
#define SM_XLO 17408
#define SM_WHI 34816
#define SM_WLO 69632
#define SM_TOTAL 104448

__global__ __launch_bounds__(256) void gemm3_raw(
    const __nv_bfloat16* __restrict__ Hhi, const __nv_bfloat16* __restrict__ Hlo,
    int wslot,
    float* __restrict__ R1, float* __restrict__ R2, float* __restrict__ R3, int M)
{
    extern __shared__ char smem[];
    __nv_bfloat16* Xhi = (__nv_bfloat16*)(smem + SM_XHI);
    __nv_bfloat16* Xlo = (__nv_bfloat16*)(smem + SM_XLO);
    __nv_bfloat16* Whi = (__nv_bfloat16*)(smem + SM_WHI);
    __nv_bfloat16* Wlo = (__nv_bfloat16*)(smem + SM_WLO);

    int tid = threadIdx.x;
    int wid = tid >> 5;
    int warpM = wid & 1;      // 2 x 32-row slices
    int warpN = wid >> 1;     // 4 x 32-col slices
    int m0 = blockIdx.x * 64;

    // stage X tile (64 x 128, hi/lo), zero-fill OOB rows
    for (int idx = tid; idx < 64 * 16; idx += 256) {
        int row = idx >> 4, c8 = (idx & 15) * 8;
        float4 zero = make_float4(0.f, 0.f, 0.f, 0.f);
        float4 vh = zero, vl = zero;
        if (m0 + row < M) {
            vh = *reinterpret_cast<const float4*>(Hhi + (size_t)(m0 + row) * D + c8);
            vl = *reinterpret_cast<const float4*>(Hlo + (size_t)(m0 + row) * D + c8);
        }
        *reinterpret_cast<float4*>(Xhi + row * XLD + c8) = vh;
        *reinterpret_cast<float4*>(Xlo + row * XLD + c8) = vl;
    }

    float* Rs[3] = {R1, R2, R3};

    for (int widx = 0; widx < 3; widx++) {
        __syncthreads();   // X staged (first) / W consumed by MMA (later)
        // ---- stage W: pure bf16 copy from pre-converted global ----
        const __nv_bfloat16* Gh = g_Whi + (size_t)(wslot + widx) * D * D;
        const __nv_bfloat16* Gl = g_Wlo + (size_t)(wslot + widx) * D * D;
        for (int idx = tid; idx < 128 * 16; idx += 256) {
            int row = idx >> 4, c8 = (idx & 15) * 8;
            *reinterpret_cast<float4*>(Whi + row * XLD + c8) =
                *reinterpret_cast<const float4*>(Gh + row * D + c8);
            *reinterpret_cast<float4*>(Wlo + row * XLD + c8) =
                *reinterpret_cast<const float4*>(Gl + row * D + c8);
        }
        __syncthreads();

        wmma::fragment<wmma::accumulator, 16, 16, 16, float> acc[2][2];
#pragma unroll
        for (int i = 0; i < 2; i++)
#pragma unroll
            for (int j = 0; j < 2; j++) wmma::fill_fragment(acc[i][j], 0.f);

#pragma unroll
        for (int kk = 0; kk < 8; kk++) {
            wmma::fragment<wmma::matrix_a, 16, 16, 16, __nv_bfloat16, wmma::row_major> ah[2], al[2];
#pragma unroll
            for (int i = 0; i < 2; i++) {
                int off = (warpM * 32 + i * 16) * XLD + kk * 16;
                wmma::load_matrix_sync(ah[i], Xhi + off, XLD);
                wmma::load_matrix_sync(al[i], Xlo + off, XLD);
            }
#pragma unroll
            for (int j = 0; j < 2; j++) {
                wmma::fragment<wmma::matrix_b, 16, 16, 16, __nv_bfloat16, wmma::row_major> bh, bl;
                int off = (kk * 16) * XLD + warpN * 32 + j * 16;
                wmma::load_matrix_sync(bh, Whi + off, XLD);
                wmma::load_matrix_sync(bl, Wlo + off, XLD);
#pragma unroll
                for (int i = 0; i < 2; i++) {
                    wmma::mma_sync(acc[i][j], ah[i], bh, acc[i][j]);
                    wmma::mma_sync(acc[i][j], ah[i], bl, acc[i][j]);
                    wmma::mma_sync(acc[i][j], al[i], bh, acc[i][j]);
                }
            }
        }

        float* R = Rs[widx];
#pragma unroll
        for (int i = 0; i < 2; i++)
#pragma unroll
            for (int j = 0; j < 2; j++)
                wmma::store_matrix_sync(
                    R + (size_t)(m0 + warpM * 32 + i * 16) * D + warpN * 32 + j * 16,
                    acc[i][j], D, wmma::mem_row_major);
    }
}

// ---------- combine + gather + LayerNorm + LeakyReLU fused (warp per row) ----
__global__ __launch_bounds__(256) void gather_ln_kernel(
    const float* __restrict__ R1, const float* __restrict__ R2, const float* __restrict__ R3,
    const float* __restrict__ b1, const float* __restrict__ b3,
    const float* __restrict__ g, const float* __restrict__ beta, int N)
{
    int row = (blockIdx.x * blockDim.x + threadIdx.x) >> 5;
    int lane = threadIdx.x & 31;
    if (row >= N) return;

    int c = lane * 4;
    size_t base = (size_t)row * D + c;
    float ws = g_wsum[row];
    float4 r3 = *reinterpret_cast<const float4*>(R3 + base);
    float4 r2 = *reinterpret_cast<const float4*>(R2 + base);
    float4 b3v = *reinterpret_cast<const float4*>(b3 + c);
    float4 b1v = *reinterpret_cast<const float4*>(b1 + c);
    float4 acc;
    acc.x = r3.x + b3v.x - ws * r2.x;
    acc.y = r3.y + b3v.y - ws * r2.y;
    acc.z = r3.z + b3v.z - ws * r2.z;
    acc.w = r3.w + b3v.w - ws * r2.w;

    int beg = g_rowptr[row], end = g_rowptr[row + 1];
    for (int chunk = beg; chunk < end; chunk += 32) {
        int idx = chunk + lane;
        int s = 0; float wv = 0.f;
        if (idx < end) { s = g_csrc[idx]; wv = g_cw[idx]; }
        int cnt = min(32, end - chunk);
#pragma unroll 4
        for (int j = 0; j < cnt; j++) {
            int ss = __shfl_sync(0xFFFFFFFFu, s, j);
            float ww = __shfl_sync(0xFFFFFFFFu, wv, j);
            float4 v = *reinterpret_cast<const float4*>(R1 + (size_t)ss * D + c);
            acc.x += ww * (v.x + b1v.x);
            acc.y += ww * (v.y + b1v.y);
            acc.z += ww * (v.z + b1v.z);
            acc.w += ww * (v.w + b1v.w);
        }
    }

    float v0 = acc.x, v1 = acc.y, v2 = acc.z, v3 = acc.w;
    float s = v0 + v1 + v2 + v3;
    float ss = v0 * v0 + v1 * v1 + v2 * v2 + v3 * v3;
#pragma unroll
    for (int o = 16; o; o >>= 1) {
        s += __shfl_xor_sync(0xFFFFFFFFu, s, o);
        ss += __shfl_xor_sync(0xFFFFFFFFu, ss, o);
    }
    float mean = s * (1.f / (float)D);
    float var = ss * (1.f / (float)D) - mean * mean;
    float inv = rsqrtf(var + 1e-5f);
    float4 gg = *reinterpret_cast<const float4*>(g + c);
    float4 bb = *reinterpret_cast<const float4*>(beta + c);
    float y0 = (v0 - mean) * inv * gg.x + bb.x;
    float y1 = (v1 - mean) * inv * gg.y + bb.y;
    float y2 = (v2 - mean) * inv * gg.z + bb.z;
    float y3 = (v3 - mean) * inv * gg.w + bb.w;
    y0 = y0 > 0.f ? y0 : 0.1f * y0;
    y1 = y1 > 0.f ? y1 : 0.1f * y1;
    y2 = y2 > 0.f ? y2 : 0.1f * y2;
    y3 = y3 > 0.f ? y3 : 0.1f * y3;
    write_hilo(base, y0, y1, y2, y3);
}

// ---------------- final layer (D -> 1): warp-per-row GEMV --------------------
__global__ void final_gemv_kernel(
    const float* __restrict__ W1, const float* __restrict__ b1,
    const float* __restrict__ W2,
    const float* __restrict__ W3, const float* __restrict__ b3,
    float* __restrict__ out, int N)
{
    int row = (blockIdx.x * blockDim.x + threadIdx.x) >> 5;
    int lane = threadIdx.x & 31;
    if (row >= N) return;
    size_t base = (size_t)row * D + lane * 4;
    float h[4];
#pragma unroll
    for (int k = 0; k < 4; k++)
        h[k] = __bfloat162float(g_Hhi[base + k]) + __bfloat162float(g_Hlo[base + k]);
    float4 w1 = *reinterpret_cast<const float4*>(W1 + lane * 4);
    float4 w2 = *reinterpret_cast<const float4*>(W2 + lane * 4);
    float4 w3 = *reinterpret_cast<const float4*>(W3 + lane * 4);
    float s1 = h[0] * w1.x + h[1] * w1.y + h[2] * w1.z + h[3] * w1.w;
    float s2 = h[0] * w2.x + h[1] * w2.y + h[2] * w2.z + h[3] * w2.w;
    float s3 = h[0] * w3.x + h[1] * w3.y + h[2] * w3.z + h[3] * w3.w;
#pragma unroll
    for (int o = 16; o; o >>= 1) {
        s1 += __shfl_xor_sync(0xFFFFFFFFu, s1, o);
        s2 += __shfl_xor_sync(0xFFFFFFFFu, s2, o);
        s3 += __shfl_xor_sync(0xFFFFFFFFu, s3, o);
    }
    if (lane == 0) {
        g_aO[row] = s1 + b1[0];
        out[row] = (s3 + b3[0]) - g_wsum[row] * s2;
    }
}

__global__ void final_gather_sigmoid_kernel(float* __restrict__ out, int N) {
    int r = blockIdx.x * blockDim.x + threadIdx.x;
    if (r >= N) return;
    float v = out[r];
    int beg = g_rowptr[r], end = g_rowptr[r + 1];
    for (int i = beg; i < end; i++) v += g_cw[i] * g_aO[g_csrc[i]];
    out[r] = 1.f / (1.f + expf(-v));
}

// ---------------- driver -----------------------------------------------------
extern "C" void kernel_launch(void* const* d_in, const int* in_sizes, int n_in,
                              void* d_out, int out_size)
{
    const float* x     = (const float*)d_in[0];
    const float* ew    = (const float*)d_in[1];
    const float* W1_in = (const float*)d_in[2];
    const float* b1_in = (const float*)d_in[3];
    const float* W2_in = (const float*)d_in[4];
    const float* W3_in = (const float*)d_in[5];
    const float* b3_in = (const float*)d_in[6];
    const float* W1_h  = (const float*)d_in[7];
    const float* b1_h  = (const float*)d_in[8];
    const float* W2_h  = (const float*)d_in[9];
    const float* W3_h  = (const float*)d_in[10];
    const float* b3_h  = (const float*)d_in[11];
    const float* W1_o  = (const float*)d_in[12];
    const float* b1_o  = (const float*)d_in[13];
    const float* W2_o  = (const float*)d_in[14];
    const float* W3_o  = (const float*)d_in[15];
    const float* b3_o  = (const float*)d_in[16];
    const float* g1    = (const float*)d_in[17];
    const float* be1   = (const float*)d_in[18];
    const float* g2    = (const float*)d_in[19];
    const float* be2   = (const float*)d_in[20];
    const int*   ei    = (const int*)d_in[21];

    int N = in_sizes[0] / D;
    int E = in_sizes[1];
    const int* src = ei;
    const int* dst = ei + E;
    float* out = (float*)d_out;

    float *R1, *R2, *R3, *colsum, *colsumsq;
    int *deg;
    __nv_bfloat16 *Hhi, *Hlo;
    cudaGetSymbolAddress((void**)&Hhi, g_Hhi);
    cudaGetSymbolAddress((void**)&Hlo, g_Hlo);
    cudaGetSymbolAddress((void**)&R1, g_R1);
    cudaGetSymbolAddress((void**)&R2, g_R2);
    cudaGetSymbolAddress((void**)&R3, g_R3);
    cudaGetSymbolAddress((void**)&colsum, g_colsum);
    cudaGetSymbolAddress((void**)&colsumsq, g_colsumsq);
    cudaGetSymbolAddress((void**)&deg, g_deg);

    static int smemSet = 0;
    if (!smemSet) {
        cudaFuncSetAttribute(gemm3_raw, cudaFuncAttributeMaxDynamicSharedMemorySize, SM_TOTAL);
        smemSet = 1;
    }

    int n4 = N * (D / 4);
    int nb = (N + 255) / 256;

    // ---- input standardization -> Hhi/Hlo ----
    zero_f<<<1, 128>>>(colsum, D);
    zero_f<<<1, 128>>>(colsumsq, D);
    colstats_kernel<<<296, 128>>>(x, N);
    colfinal_kernel<<<1, 128>>>(N);
    normalize_kernel<<<(n4 + 255) / 256, 256>>>((const float4*)x, n4);

    // ---- weight pre-conversion ----
    WPtrs wp;
    wp.w[0] = W1_in; wp.w[1] = W2_in; wp.w[2] = W3_in;
    wp.w[3] = W1_h;  wp.w[4] = W2_h;  wp.w[5] = W3_h;
    convert_w_kernel<<<dim3(D * D / 4 / 256, 6), 256>>>(wp);

    // ---- CSR build ----
    zero_i<<<nb, 256>>>(deg, N);
    deg_hist_kernel<<<(E + 255) / 256, 256>>>(dst, E);
    scan1_kernel<<<nb, 256>>>(N);
    scan2_kernel<<<1, 256>>>(nb);
    scan3_kernel<<<nb, 256>>>(N);
    csr_fill_kernel<<<(E + 255) / 256, 256>>>(src, dst, ew, E);
    wsum_csr_kernel<<<nb, 256>>>(N);

    // ---- 3 full LEConv layers ----
    struct LW { int slot; const float *b1, *b3, *g, *be; };
    LW layers[1 + NUM_INNER];
    layers[0] = {0, b1_in, b3_in, g1, be1};
    for (int l = 1; l <= NUM_INNER; l++)
        layers[l] = {3, b1_h, b3_h, g2, be2};

    int gemmGrid = (N + 63) / 64;
    for (int l = 0; l < 1 + NUM_INNER; l++) {
        gemm3_raw<<<gemmGrid, 256, SM_TOTAL>>>(Hhi, Hlo, layers[l].slot, R1, R2, R3, N);
        gather_ln_kernel<<<(N + 7) / 8, 256>>>(R1, R2, R3, layers[l].b1, layers[l].b3,
                                               layers[l].g, layers[l].be, N);
    }

    // ---- output layer (D -> 1) + sigmoid ----
    final_gemv_kernel<<<(N + 7) / 8, 256>>>(W1_o, b1_o, W2_o, W3_o, b3_o, out, N);
    final_gather_sigmoid_kernel<<<nb, 256>>>(out, N);
}